// round 11
// baseline (speedup 1.0000x reference)
#include <cuda_runtime.h>
#include <cuda_bf16.h>
#include <math.h>

#define N_ENT 100000
#define DIM   128
#define NB    50000
#define NR    8
#define NE    200000

// ---------------------------------------------------------------------------
// Device scratch
// ---------------------------------------------------------------------------
__device__ float    g_Te[(size_t)N_ENT * DIM];   // transformed embeddings (current rel)
__device__ float    g_Z [(size_t)N_ENT * DIM];   // accumulator
// packed bf16x2 (k-pairs) operands, row pitch 64 words (=128 k)
__device__ unsigned g_Ah[(size_t)N_ENT * 64], g_Al[(size_t)N_ENT * 64];
__device__ unsigned g_Hh[(size_t)NB * 64],    g_Hl[(size_t)NB * 64];
__device__ unsigned g_Th[(size_t)NB * 64],    g_Tl[(size_t)NB * 64];
// packed weights: [9 mats][n=128][kp=64], mat 8 = self kernel
__device__ unsigned g_Wh[9 * 128 * 64],       g_Wl[9 * 128 * 64];

// ---------------------------------------------------------------------------
// bf16 split/pack helpers
// ---------------------------------------------------------------------------
__device__ __forceinline__ void split_pack(float x, unsigned short& h, unsigned short& l) {
    __nv_bfloat16 hb = __float2bfloat16(x);
    float hf = __bfloat162float(hb);
    __nv_bfloat16 lb = __float2bfloat16(x - hf);
    h = __bfloat16_as_ushort(hb);
    l = __bfloat16_as_ushort(lb);
}

__global__ void __launch_bounds__(256) pack_rows(const float* __restrict__ src,
                                                 int dsel, int nwords) {
    int w = blockIdx.x * 256 + threadIdx.x;
    if (w >= nwords) return;
    unsigned* hi = dsel == 0 ? g_Ah : (dsel == 1 ? g_Hh : g_Th);
    unsigned* lo = dsel == 0 ? g_Al : (dsel == 1 ? g_Hl : g_Tl);
    float2 v = *reinterpret_cast<const float2*>(src + 2 * (size_t)w);
    unsigned short h0, l0, h1, l1;
    split_pack(v.x, h0, l0);
    split_pack(v.y, h1, l1);
    hi[w] = (unsigned)h0 | ((unsigned)h1 << 16);
    lo[w] = (unsigned)l0 | ((unsigned)l1 << 16);
}

__global__ void __launch_bounds__(256) pack_w(const float* __restrict__ src,
                                              int dst_off) {
    int mat = blockIdx.y;
    const float* W = src + (size_t)mat * 128 * 128;
    int idx = blockIdx.x * 256 + threadIdx.x;   // 0..8191
    int n  = idx & 127;
    int kp = idx >> 7;                          // 0..63
    float a = W[(2 * kp) * 128 + n];
    float b = W[(2 * kp + 1) * 128 + n];
    unsigned short h0, l0, h1, l1;
    split_pack(a, h0, l0);
    split_pack(b, h1, l1);
    int w = dst_off + mat * 8192 + n * 64 + kp;
    g_Wh[w] = (unsigned)h0 | ((unsigned)h1 << 16);
    g_Wl[w] = (unsigned)l0 | ((unsigned)l1 << 16);
}

__global__ void __launch_bounds__(256) zero_Z_k() {
    const int n4 = N_ENT * DIM / 4;
    float4 z = make_float4(0.f, 0.f, 0.f, 0.f);
    for (int i = blockIdx.x * blockDim.x + threadIdx.x; i < n4;
         i += gridDim.x * blockDim.x) {
        reinterpret_cast<float4*>(g_Z)[i] = z;
    }
}

// ---------------------------------------------------------------------------
// mma + ldmatrix wrappers
// ---------------------------------------------------------------------------
__device__ __forceinline__ void mma_bf16(float* c, const unsigned* a, const unsigned* b) {
    asm volatile(
        "mma.sync.aligned.m16n8k16.row.col.f32.bf16.bf16.f32 "
        "{%0,%1,%2,%3}, {%4,%5,%6,%7}, {%8,%9}, {%0,%1,%2,%3};"
        : "+f"(c[0]), "+f"(c[1]), "+f"(c[2]), "+f"(c[3])
        : "r"(a[0]), "r"(a[1]), "r"(a[2]), "r"(a[3]), "r"(b[0]), "r"(b[1]));
}
__device__ __forceinline__ void ldm_x4(unsigned* r, unsigned saddr) {
    asm volatile("ldmatrix.sync.aligned.m8n8.x4.shared.b16 {%0,%1,%2,%3}, [%4];"
                 : "=r"(r[0]), "=r"(r[1]), "=r"(r[2]), "=r"(r[3]) : "r"(saddr));
}

// ---------------------------------------------------------------------------
// GEMM core v2: FULL K=128 resident in smem, ONE __syncthreads, then 8
// uninterrupted ks-steps of LDSM+MMA. bf16 3-product split, pre-packed.
// 256 thr = 8 warps (2m x 4n), warp tile 32x32.
// EPI=0: -> g_Te.  EPI=1: out = sigmoid(C + Z[idx[row]]).
// ---------------------------------------------------------------------------
#define PA 68   // word pitch; 68 mod 32 = 4 -> conflict-free ldmatrix rows
#define SMEM_WORDS (64 * PA * 2 + 128 * PA * 2)      // 26112
#define SMEM_BYTES (SMEM_WORDS * 4)                  // 104448

template <int EPI>
__device__ __forceinline__ void gemm_core(int asel, int woff,
                                          const int* __restrict__ idx,
                                          float* __restrict__ out, int M) {
    extern __shared__ unsigned sm[];
    unsigned* Ash = sm;                       // [64][PA]
    unsigned* Asl = sm + 64 * PA;
    unsigned* Wsh = sm + 2 * 64 * PA;         // [128][PA]
    unsigned* Wsl = sm + 2 * 64 * PA + 128 * PA;

    const unsigned* Ah = asel == 0 ? g_Ah : (asel == 1 ? g_Hh : g_Th);
    const unsigned* Al = asel == 0 ? g_Al : (asel == 1 ? g_Hl : g_Tl);
    const unsigned* Wh = g_Wh + woff;
    const unsigned* Wl = g_Wl + woff;

    const int tid    = threadIdx.x;
    const int lane   = tid & 31;
    const int wid    = tid >> 5;
    const int warp_m = wid >> 2;
    const int warp_n = wid & 3;
    const int m0     = blockIdx.x * 64;
    const int gq     = lane >> 2;
    const int tg     = lane & 3;
    const int lane8  = lane & 7;
    const int tsel   = lane >> 3;

    unsigned sAh = (unsigned)__cvta_generic_to_shared(Ash);
    unsigned sAl = (unsigned)__cvta_generic_to_shared(Asl);
    unsigned sWh = (unsigned)__cvta_generic_to_shared(Wsh);
    unsigned sWl = (unsigned)__cvta_generic_to_shared(Wsl);

    // ---- load full A tile: 64 rows x 64 words (4 thr/row, 4 uint4 each) ----
    {
        int row = tid >> 2, q = tid & 3;
        int gr = m0 + row;
#pragma unroll
        for (int j = 0; j < 4; j++) {
            int w0 = q * 16 + j * 4;
            uint4 vh = make_uint4(0, 0, 0, 0), vl = make_uint4(0, 0, 0, 0);
            if (gr < M) {
                size_t s = (size_t)gr * 64 + w0;
                vh = *reinterpret_cast<const uint4*>(Ah + s);
                vl = *reinterpret_cast<const uint4*>(Al + s);
            }
            int d = row * PA + w0;
            *reinterpret_cast<uint4*>(Ash + d) = vh;
            *reinterpret_cast<uint4*>(Asl + d) = vl;
        }
    }
    // ---- load full W tile: 128 n x 64 words ----
#pragma unroll
    for (int i = 0; i < 2; i++) {
        int li = tid + i * 256;
        int n = li >> 2, q = li & 3;
#pragma unroll
        for (int j = 0; j < 4; j++) {
            int w0 = q * 16 + j * 4;
            size_t s = (size_t)n * 64 + w0;
            int d = n * PA + w0;
            *reinterpret_cast<uint4*>(Wsh + d) = *reinterpret_cast<const uint4*>(Wh + s);
            *reinterpret_cast<uint4*>(Wsl + d) = *reinterpret_cast<const uint4*>(Wl + s);
        }
    }
    __syncthreads();   // the only barrier

    float acc[2][4][4];
#pragma unroll
    for (int i = 0; i < 2; i++)
#pragma unroll
        for (int j = 0; j < 4; j++)
#pragma unroll
            for (int k = 0; k < 4; k++) acc[i][j][k] = 0.f;

#pragma unroll
    for (int ks = 0; ks < 8; ks++) {
        const int kpb = ks * 8;
        unsigned ahi[2][4], alo[2][4];
#pragma unroll
        for (int mt = 0; mt < 2; mt++) {
            int arow = warp_m * 32 + mt * 16 + (tsel & 1) * 8 + lane8;
            int akp  = kpb + (tsel >> 1) * 4;
            unsigned off = (unsigned)(arow * PA + akp) * 4u;
            ldm_x4(ahi[mt], sAh + off);
            ldm_x4(alo[mt], sAl + off);
        }
#pragma unroll
        for (int np = 0; np < 2; np++) {
            int brow = warp_n * 32 + np * 16 + (tsel >> 1) * 8 + lane8;
            int bkp  = kpb + (tsel & 1) * 4;
            unsigned off = (unsigned)(brow * PA + bkp) * 4u;
            unsigned bh[4], bl[4];
            ldm_x4(bh, sWh + off);
            ldm_x4(bl, sWl + off);
#pragma unroll
            for (int nn = 0; nn < 2; nn++)
#pragma unroll
                for (int mt = 0; mt < 2; mt++) {
                    float* c = acc[mt][np * 2 + nn];
                    mma_bf16(c, ahi[mt], &bh[nn * 2]);
                    mma_bf16(c, alo[mt], &bh[nn * 2]);
                    mma_bf16(c, ahi[mt], &bl[nn * 2]);
                }
        }
    }

    // epilogue: c0,c1 @ (row gq, cols 2tg,2tg+1); c2,c3 @ row gq+8
#pragma unroll
    for (int mt = 0; mt < 2; mt++) {
#pragma unroll
        for (int half = 0; half < 2; half++) {
            int gr = m0 + warp_m * 32 + mt * 16 + gq + half * 8;
            if (gr >= M) continue;
            if (EPI == 0) {
#pragma unroll
                for (int nt = 0; nt < 4; nt++) {
                    int col = warp_n * 32 + nt * 8 + 2 * tg;
                    float2 v = make_float2(acc[mt][nt][half * 2 + 0],
                                           acc[mt][nt][half * 2 + 1]);
                    *reinterpret_cast<float2*>(&g_Te[(size_t)gr * 128 + col]) = v;
                }
            } else {
                int node = __ldg(&idx[gr]);
#pragma unroll
                for (int nt = 0; nt < 4; nt++) {
                    int col = warp_n * 32 + nt * 8 + 2 * tg;
                    float2 z = *reinterpret_cast<const float2*>(&g_Z[(size_t)node * 128 + col]);
                    float2 o;
                    o.x = 1.f / (1.f + expf(-(acc[mt][nt][half * 2 + 0] + z.x)));
                    o.y = 1.f / (1.f + expf(-(acc[mt][nt][half * 2 + 1] + z.y)));
                    *reinterpret_cast<float2*>(&out[(size_t)gr * 128 + col]) = o;
                }
            }
        }
    }
}

__global__ void __launch_bounds__(256, 2) gemm_te_tc(int woff, int M) {
    gemm_core<0>(0, woff, nullptr, nullptr, M);
}
__global__ void __launch_bounds__(256, 2) out_tc(int asel, int woff,
                                                 const int* __restrict__ idx,
                                                 float* __restrict__ out, int M) {
    gemm_core<1>(asel, woff, idx, out, M);
}

// ---------------------------------------------------------------------------
// Scatter: 64 edges per block, 8 per warp, indices staged in smem,
// all 8 Te reads issued before the 8 red.v4 ops (MLP=8).
// ---------------------------------------------------------------------------
#define EPB 64
__global__ void __launch_bounds__(256) scatter_k(const int*   __restrict__ src,
                                                 const int*   __restrict__ dst,
                                                 const float* __restrict__ val) {
    __shared__ int   sS[EPB];
    __shared__ int   sD[EPB];
    __shared__ float sV[EPB];
    const int base = blockIdx.x * EPB;
    const int tid  = threadIdx.x;
    if (tid < EPB)                sS[tid]           = __ldg(&src[base + tid]);
    else if (tid < 2 * EPB)       sD[tid - EPB]     = __ldg(&dst[base + tid - EPB]);
    else if (tid < 3 * EPB)       sV[tid - 2 * EPB] = __ldg(&val[base + tid - 2 * EPB]);
    __syncthreads();

    const int wid  = tid >> 5;
    const int lane = tid & 31;
    const int e0   = wid * 8;

    float4 t[8];
#pragma unroll
    for (int i = 0; i < 8; i++) {
        int d = sD[e0 + i];
        t[i] = *reinterpret_cast<const float4*>(&g_Te[(size_t)d * 128 + lane * 4]);
    }
#pragma unroll
    for (int i = 0; i < 8; i++) {
        float v = sV[e0 + i];
        float* zp = &g_Z[(size_t)sS[e0 + i] * 128 + lane * 4];
        asm volatile("red.global.add.v4.f32 [%0], {%1, %2, %3, %4};"
                     :: "l"(zp), "f"(t[i].x * v), "f"(t[i].y * v),
                        "f"(t[i].z * v), "f"(t[i].w * v)
                     : "memory");
    }
}

// ---------------------------------------------------------------------------
// Launch
// ---------------------------------------------------------------------------
extern "C" void kernel_launch(void* const* d_in, const int* in_sizes, int n_in,
                              void* d_out, int out_size) {
    const float* emb      = (const float*)d_in[0];
    const float* head_e   = (const float*)d_in[1];
    const float* tail_e   = (const float*)d_in[2];
    const float* relk     = (const float*)d_in[3];
    const float* selfk    = (const float*)d_in[4];
    const float* edge_val = (const float*)d_in[5];
    const int*   head_idx = (const int*)d_in[6];
    const int*   tail_idx = (const int*)d_in[7];
    const int*   edge_src = (const int*)d_in[8];
    const int*   edge_dst = (const int*)d_in[9];
    float*       out      = (float*)d_out;        // [2, B, 128], head first

    static bool attr_done = false;
    if (!attr_done) {   // first call is the uncaptured correctness run
        cudaFuncSetAttribute(gemm_te_tc, cudaFuncAttributeMaxDynamicSharedMemorySize, SMEM_BYTES);
        cudaFuncSetAttribute(out_tc,     cudaFuncAttributeMaxDynamicSharedMemorySize, SMEM_BYTES);
        attr_done = true;
    }

    pack_rows<<<(N_ENT * 64 + 255) / 256, 256>>>(emb,    0, N_ENT * 64);
    pack_rows<<<(NB * 64 + 255) / 256, 256>>>(head_e, 1, NB * 64);
    pack_rows<<<(NB * 64 + 255) / 256, 256>>>(tail_e, 2, NB * 64);
    pack_w<<<dim3(32, NR), 256>>>(relk, 0);
    pack_w<<<dim3(32, 1), 256>>>(selfk, NR * 8192);
    zero_Z_k<<<2048, 256>>>();

    const int gemm_blocks = (N_ENT + 63) / 64;   // 1563
    const int scat_blocks = NE / EPB;            // 3125
    for (int r = 0; r < NR; r++) {
        gemm_te_tc<<<gemm_blocks, 256, SMEM_BYTES>>>(r * 8192, N_ENT);
        scatter_k<<<scat_blocks, 256>>>(edge_src + (size_t)r * NE,
                                        edge_dst + (size_t)r * NE,
                                        edge_val + (size_t)r * NE);
    }

    const int out_blocks = (NB + 63) / 64;       // 782
    out_tc<<<out_blocks, 256, SMEM_BYTES>>>(1, NR * 8192, head_idx, out, NB);
    out_tc<<<out_blocks, 256, SMEM_BYTES>>>(2, NR * 8192, tail_idx,
                                            out + (size_t)NB * 128, NB);
}

// round 13
// speedup vs baseline: 1.2478x; 1.2478x over previous
#include <cuda_runtime.h>
#include <cuda_bf16.h>
#include <math.h>

#define N_ENT 100000
#define DIM   128
#define NB    50000
#define NR    8
#define NE    200000

// ---------------------------------------------------------------------------
// Device scratch
// ---------------------------------------------------------------------------
__device__ float    g_Te [(size_t)N_ENT * DIM];  // ping
__device__ float    g_Te2[(size_t)N_ENT * DIM];  // pong
__device__ float    g_Z  [(size_t)N_ENT * DIM];  // accumulator
// packed bf16x2 (k-pairs) operands, row pitch 64 words (=128 k)
__device__ unsigned g_Ah[(size_t)N_ENT * 64], g_Al[(size_t)N_ENT * 64];
__device__ unsigned g_Hh[(size_t)NB * 64],    g_Hl[(size_t)NB * 64];
__device__ unsigned g_Th[(size_t)NB * 64],    g_Tl[(size_t)NB * 64];
// packed weights: [9 mats][n=128][kp=64], mat 8 = self kernel
__device__ unsigned g_Wh[9 * 128 * 64],       g_Wl[9 * 128 * 64];

// ---------------------------------------------------------------------------
// bf16 split/pack helpers
// ---------------------------------------------------------------------------
__device__ __forceinline__ void split_pack(float x, unsigned short& h, unsigned short& l) {
    __nv_bfloat16 hb = __float2bfloat16(x);
    float hf = __bfloat162float(hb);
    __nv_bfloat16 lb = __float2bfloat16(x - hf);
    h = __bfloat16_as_ushort(hb);
    l = __bfloat16_as_ushort(lb);
}

__global__ void __launch_bounds__(256) pack_rows(const float* __restrict__ src,
                                                 int dsel, int nwords) {
    int w = blockIdx.x * 256 + threadIdx.x;
    if (w >= nwords) return;
    unsigned* hi = dsel == 0 ? g_Ah : (dsel == 1 ? g_Hh : g_Th);
    unsigned* lo = dsel == 0 ? g_Al : (dsel == 1 ? g_Hl : g_Tl);
    float2 v = *reinterpret_cast<const float2*>(src + 2 * (size_t)w);
    unsigned short h0, l0, h1, l1;
    split_pack(v.x, h0, l0);
    split_pack(v.y, h1, l1);
    hi[w] = (unsigned)h0 | ((unsigned)h1 << 16);
    lo[w] = (unsigned)l0 | ((unsigned)l1 << 16);
}

__global__ void __launch_bounds__(256) pack_w(const float* __restrict__ src,
                                              int dst_off) {
    int mat = blockIdx.y;
    const float* W = src + (size_t)mat * 128 * 128;
    int idx = blockIdx.x * 256 + threadIdx.x;   // 0..8191
    int n  = idx & 127;
    int kp = idx >> 7;                          // 0..63
    float a = W[(2 * kp) * 128 + n];
    float b = W[(2 * kp + 1) * 128 + n];
    unsigned short h0, l0, h1, l1;
    split_pack(a, h0, l0);
    split_pack(b, h1, l1);
    int w = dst_off + mat * 8192 + n * 64 + kp;
    g_Wh[w] = (unsigned)h0 | ((unsigned)h1 << 16);
    g_Wl[w] = (unsigned)l0 | ((unsigned)l1 << 16);
}

__global__ void __launch_bounds__(256) zero_Z_k() {
    const int n4 = N_ENT * DIM / 4;
    float4 z = make_float4(0.f, 0.f, 0.f, 0.f);
    for (int i = blockIdx.x * blockDim.x + threadIdx.x; i < n4;
         i += gridDim.x * blockDim.x) {
        reinterpret_cast<float4*>(g_Z)[i] = z;
    }
}

// ---------------------------------------------------------------------------
// mma + ldmatrix wrappers
// ---------------------------------------------------------------------------
__device__ __forceinline__ void mma_bf16(float* c, const unsigned* a, const unsigned* b) {
    asm volatile(
        "mma.sync.aligned.m16n8k16.row.col.f32.bf16.bf16.f32 "
        "{%0,%1,%2,%3}, {%4,%5,%6,%7}, {%8,%9}, {%0,%1,%2,%3};"
        : "+f"(c[0]), "+f"(c[1]), "+f"(c[2]), "+f"(c[3])
        : "r"(a[0]), "r"(a[1]), "r"(a[2]), "r"(a[3]), "r"(b[0]), "r"(b[1]));
}
__device__ __forceinline__ void ldm_x4(unsigned* r, unsigned saddr) {
    asm volatile("ldmatrix.sync.aligned.m8n8.x4.shared.b16 {%0,%1,%2,%3}, [%4];"
                 : "=r"(r[0]), "=r"(r[1]), "=r"(r[2]), "=r"(r[3]) : "r"(saddr));
}

// ---------------------------------------------------------------------------
// GEMM core (R9-proven: BK=32 pipelined, bf16 3-product split, pre-packed).
// EPI=0: -> Te buffer (bsel).  EPI=1: out = sigmoid(C + Z[idx[row]]).
// ---------------------------------------------------------------------------
#define PITCH 20
template <int EPI>
__device__ __forceinline__ void gemm_core(int asel, int woff, int bsel,
                                          const int* __restrict__ idx,
                                          float* __restrict__ out, int M) {
    __shared__ unsigned Ash[64 * PITCH], Asl[64 * PITCH];
    __shared__ unsigned Wsh[128 * PITCH], Wsl[128 * PITCH];

    const unsigned* Ah = asel == 0 ? g_Ah : (asel == 1 ? g_Hh : g_Th);
    const unsigned* Al = asel == 0 ? g_Al : (asel == 1 ? g_Hl : g_Tl);
    const unsigned* Wh = g_Wh + woff;
    const unsigned* Wl = g_Wl + woff;
    float* Te = bsel ? g_Te2 : g_Te;

    const int tid    = threadIdx.x;
    const int lane   = tid & 31;
    const int wid    = tid >> 5;
    const int warp_m = wid >> 2;
    const int warp_n = wid & 3;
    const int m0     = blockIdx.x * 64;
    const int gq     = lane >> 2;
    const int tg     = lane & 3;
    const int lane8  = lane & 7;
    const int tsel   = lane >> 3;

    unsigned sAh = (unsigned)__cvta_generic_to_shared(Ash);
    unsigned sAl = (unsigned)__cvta_generic_to_shared(Asl);
    unsigned sWh = (unsigned)__cvta_generic_to_shared(Wsh);
    unsigned sWl = (unsigned)__cvta_generic_to_shared(Wsl);

    float acc[2][4][4];
#pragma unroll
    for (int i = 0; i < 2; i++)
#pragma unroll
        for (int j = 0; j < 4; j++)
#pragma unroll
            for (int k = 0; k < 4; k++) acc[i][j][k] = 0.f;

#pragma unroll
    for (int kt = 0; kt < 4; kt++) {
        const int K0 = kt * 16;
        {
            int row = tid >> 2, q = tid & 3;
            int gr = m0 + row;
            uint4 vh = make_uint4(0, 0, 0, 0), vl = make_uint4(0, 0, 0, 0);
            if (gr < M) {
                size_t s = (size_t)gr * 64 + K0 + q * 4;
                vh = *reinterpret_cast<const uint4*>(Ah + s);
                vl = *reinterpret_cast<const uint4*>(Al + s);
            }
            int d = row * PITCH + q * 4;
            *reinterpret_cast<uint4*>(Ash + d) = vh;
            *reinterpret_cast<uint4*>(Asl + d) = vl;
        }
#pragma unroll
        for (int i = 0; i < 2; i++) {
            int li = tid + i * 256;
            int n = li >> 2, q = li & 3;
            size_t s = (size_t)n * 64 + K0 + q * 4;
            int d = n * PITCH + q * 4;
            *reinterpret_cast<uint4*>(Wsh + d) = *reinterpret_cast<const uint4*>(Wh + s);
            *reinterpret_cast<uint4*>(Wsl + d) = *reinterpret_cast<const uint4*>(Wl + s);
        }
        __syncthreads();

#pragma unroll
        for (int ks = 0; ks < 2; ks++) {
            const int kpb = ks * 8;
            unsigned ahi[2][4], alo[2][4];
#pragma unroll
            for (int mt = 0; mt < 2; mt++) {
                int arow = warp_m * 32 + mt * 16 + (tsel & 1) * 8 + lane8;
                int akp  = kpb + (tsel >> 1) * 4;
                unsigned off = (unsigned)(arow * PITCH + akp) * 4u;
                ldm_x4(ahi[mt], sAh + off);
                ldm_x4(alo[mt], sAl + off);
            }
#pragma unroll
            for (int np = 0; np < 2; np++) {
                int brow = warp_n * 32 + np * 16 + (tsel >> 1) * 8 + lane8;
                int bkp  = kpb + (tsel & 1) * 4;
                unsigned off = (unsigned)(brow * PITCH + bkp) * 4u;
                unsigned bh[4], bl[4];
                ldm_x4(bh, sWh + off);
                ldm_x4(bl, sWl + off);
#pragma unroll
                for (int nn = 0; nn < 2; nn++)
#pragma unroll
                    for (int mt = 0; mt < 2; mt++) {
                        float* c = acc[mt][np * 2 + nn];
                        mma_bf16(c, ahi[mt], &bh[nn * 2]);
                        mma_bf16(c, alo[mt], &bh[nn * 2]);
                        mma_bf16(c, ahi[mt], &bl[nn * 2]);
                    }
            }
        }
        __syncthreads();
    }

#pragma unroll
    for (int mt = 0; mt < 2; mt++) {
#pragma unroll
        for (int half = 0; half < 2; half++) {
            int gr = m0 + warp_m * 32 + mt * 16 + gq + half * 8;
            if (gr >= M) continue;
            if (EPI == 0) {
#pragma unroll
                for (int nt = 0; nt < 4; nt++) {
                    int col = warp_n * 32 + nt * 8 + 2 * tg;
                    float2 v = make_float2(acc[mt][nt][half * 2 + 0],
                                           acc[mt][nt][half * 2 + 1]);
                    *reinterpret_cast<float2*>(&Te[(size_t)gr * 128 + col]) = v;
                }
            } else {
                int node = __ldg(&idx[gr]);
#pragma unroll
                for (int nt = 0; nt < 4; nt++) {
                    int col = warp_n * 32 + nt * 8 + 2 * tg;
                    float2 z = *reinterpret_cast<const float2*>(&g_Z[(size_t)node * 128 + col]);
                    float2 o;
                    o.x = 1.f / (1.f + expf(-(acc[mt][nt][half * 2 + 0] + z.x)));
                    o.y = 1.f / (1.f + expf(-(acc[mt][nt][half * 2 + 1] + z.y)));
                    *reinterpret_cast<float2*>(&out[(size_t)gr * 128 + col]) = o;
                }
            }
        }
    }
}

__global__ void __launch_bounds__(256, 3) gemm_te_tc(int woff, int bsel, int M) {
    gemm_core<0>(0, woff, bsel, nullptr, nullptr, M);
}
__global__ void __launch_bounds__(256, 3) out_tc(int asel, int woff,
                                                 const int* __restrict__ idx,
                                                 float* __restrict__ out, int M) {
    gemm_core<1>(asel, woff, 0, idx, out, M);
}

// ---------------------------------------------------------------------------
// Scatter (R9-proven): 64 edges per block, 8 per warp, smem-staged indices,
// all 8 Te reads in flight before the 8 red.v4 ops (MLP=8).
// ---------------------------------------------------------------------------
#define EPB 64
__global__ void __launch_bounds__(256) scatter_k(const int*   __restrict__ src,
                                                 const int*   __restrict__ dst,
                                                 const float* __restrict__ val,
                                                 int bsel) {
    const float* Te = bsel ? g_Te2 : g_Te;
    __shared__ int   sS[EPB];
    __shared__ int   sD[EPB];
    __shared__ float sV[EPB];
    const int base = blockIdx.x * EPB;
    const int tid  = threadIdx.x;
    if (tid < EPB)                sS[tid]           = __ldg(&src[base + tid]);
    else if (tid < 2 * EPB)       sD[tid - EPB]     = __ldg(&dst[base + tid - EPB]);
    else if (tid < 3 * EPB)       sV[tid - 2 * EPB] = __ldg(&val[base + tid - 2 * EPB]);
    __syncthreads();

    const int wid  = tid >> 5;
    const int lane = tid & 31;
    const int e0   = wid * 8;

    float4 t[8];
#pragma unroll
    for (int i = 0; i < 8; i++) {
        int d = sD[e0 + i];
        t[i] = *reinterpret_cast<const float4*>(&Te[(size_t)d * 128 + lane * 4]);
    }
#pragma unroll
    for (int i = 0; i < 8; i++) {
        float v = sV[e0 + i];
        float* zp = &g_Z[(size_t)sS[e0 + i] * 128 + lane * 4];
        asm volatile("red.global.add.v4.f32 [%0], {%1, %2, %3, %4};"
                     :: "l"(zp), "f"(t[i].x * v), "f"(t[i].y * v),
                        "f"(t[i].z * v), "f"(t[i].w * v)
                     : "memory");
    }
}

// ---------------------------------------------------------------------------
// Launch: scatter chain forked to stream s2; gemm(r+1) overlaps scatter(r).
// ---------------------------------------------------------------------------
extern "C" void kernel_launch(void* const* d_in, const int* in_sizes, int n_in,
                              void* d_out, int out_size) {
    const float* emb      = (const float*)d_in[0];
    const float* head_e   = (const float*)d_in[1];
    const float* tail_e   = (const float*)d_in[2];
    const float* relk     = (const float*)d_in[3];
    const float* selfk    = (const float*)d_in[4];
    const float* edge_val = (const float*)d_in[5];
    const int*   head_idx = (const int*)d_in[6];
    const int*   tail_idx = (const int*)d_in[7];
    const int*   edge_src = (const int*)d_in[8];
    const int*   edge_dst = (const int*)d_in[9];
    float*       out      = (float*)d_out;        // [2, B, 128], head first

    static bool init = false;
    static cudaStream_t s2;
    static cudaEvent_t e_g[NR], e_s[NR];
    if (!init) {   // first call is the uncaptured correctness run
        cudaStreamCreateWithFlags(&s2, cudaStreamNonBlocking);
        for (int i = 0; i < NR; i++) {
            cudaEventCreateWithFlags(&e_g[i], cudaEventDisableTiming);
            cudaEventCreateWithFlags(&e_s[i], cudaEventDisableTiming);
        }
        init = true;
    }

    pack_rows<<<(N_ENT * 64 + 255) / 256, 256>>>(emb,    0, N_ENT * 64);
    pack_rows<<<(NB * 64 + 255) / 256, 256>>>(head_e, 1, NB * 64);
    pack_rows<<<(NB * 64 + 255) / 256, 256>>>(tail_e, 2, NB * 64);
    pack_w<<<dim3(32, NR), 256>>>(relk, 0);
    pack_w<<<dim3(32, 1), 256>>>(selfk, NR * 8192);
    zero_Z_k<<<2048, 256>>>();

    const int gemm_blocks = (N_ENT + 63) / 64;   // 1563
    const int scat_blocks = NE / EPB;            // 3125
    for (int r = 0; r < NR; r++) {
        int buf = r & 1;
        if (r >= 2) cudaStreamWaitEvent(0, e_s[r - 2], 0);  // buffer reuse guard
        gemm_te_tc<<<gemm_blocks, 256>>>(r * 8192, buf, N_ENT);
        cudaEventRecord(e_g[r], 0);
        cudaStreamWaitEvent(s2, e_g[r], 0);
        scatter_k<<<scat_blocks, 256, 0, s2>>>(edge_src + (size_t)r * NE,
                                               edge_dst + (size_t)r * NE,
                                               edge_val + (size_t)r * NE, buf);
        cudaEventRecord(e_s[r], s2);
    }
    cudaStreamWaitEvent(0, e_s[NR - 1], 0);   // join (s2 FIFO orders all scatters before it)

    const int out_blocks = (NB + 63) / 64;       // 782
    out_tc<<<out_blocks, 256>>>(1, NR * 8192, head_idx, out, NB);
    out_tc<<<out_blocks, 256>>>(2, NR * 8192, tail_idx, out + (size_t)NB * 128, NB);
}

// round 16
// speedup vs baseline: 1.2580x; 1.0082x over previous
#include <cuda_runtime.h>
#include <cuda_bf16.h>
#include <math.h>

#define N_ENT 100000
#define DIM   128
#define NB    50000
#define NR    8
#define NE    200000

// ---------------------------------------------------------------------------
// Device scratch
// ---------------------------------------------------------------------------
__device__ float    g_TeA[(size_t)4 * N_ENT * DIM];  // 4 Te buffers
__device__ float    g_Z  [(size_t)N_ENT * DIM];      // accumulator
// packed bf16x2 (k-pairs) operands, row pitch 64 words (=128 k)
__device__ unsigned g_Ah[(size_t)N_ENT * 64], g_Al[(size_t)N_ENT * 64];
__device__ unsigned g_Hh[(size_t)NB * 64],    g_Hl[(size_t)NB * 64];
__device__ unsigned g_Th[(size_t)NB * 64],    g_Tl[(size_t)NB * 64];
// packed weights: [9 mats][n=128][kp=64], mat 8 = self kernel
__device__ unsigned g_Wh[9 * 128 * 64],       g_Wl[9 * 128 * 64];

// ---------------------------------------------------------------------------
// bf16 split/pack helpers
// ---------------------------------------------------------------------------
__device__ __forceinline__ void split_pack(float x, unsigned short& h, unsigned short& l) {
    __nv_bfloat16 hb = __float2bfloat16(x);
    float hf = __bfloat162float(hb);
    __nv_bfloat16 lb = __float2bfloat16(x - hf);
    h = __bfloat16_as_ushort(hb);
    l = __bfloat16_as_ushort(lb);
}

__global__ void __launch_bounds__(256) pack_rows(const float* __restrict__ src,
                                                 int dsel, int nwords) {
    int w = blockIdx.x * 256 + threadIdx.x;
    if (w >= nwords) return;
    unsigned* hi = dsel == 0 ? g_Ah : (dsel == 1 ? g_Hh : g_Th);
    unsigned* lo = dsel == 0 ? g_Al : (dsel == 1 ? g_Hl : g_Tl);
    float2 v = *reinterpret_cast<const float2*>(src + 2 * (size_t)w);
    unsigned short h0, l0, h1, l1;
    split_pack(v.x, h0, l0);
    split_pack(v.y, h1, l1);
    hi[w] = (unsigned)h0 | ((unsigned)h1 << 16);
    lo[w] = (unsigned)l0 | ((unsigned)l1 << 16);
}

__global__ void __launch_bounds__(256) pack_w(const float* __restrict__ src,
                                              int dst_off) {
    int mat = blockIdx.y;
    const float* W = src + (size_t)mat * 128 * 128;
    int idx = blockIdx.x * 256 + threadIdx.x;   // 0..8191
    int n  = idx & 127;
    int kp = idx >> 7;                          // 0..63
    float a = W[(2 * kp) * 128 + n];
    float b = W[(2 * kp + 1) * 128 + n];
    unsigned short h0, l0, h1, l1;
    split_pack(a, h0, l0);
    split_pack(b, h1, l1);
    int w = dst_off + mat * 8192 + n * 64 + kp;
    g_Wh[w] = (unsigned)h0 | ((unsigned)h1 << 16);
    g_Wl[w] = (unsigned)l0 | ((unsigned)l1 << 16);
}

__global__ void __launch_bounds__(256) zero_Z_k() {
    const int n4 = N_ENT * DIM / 4;
    float4 z = make_float4(0.f, 0.f, 0.f, 0.f);
    for (int i = blockIdx.x * blockDim.x + threadIdx.x; i < n4;
         i += gridDim.x * blockDim.x) {
        reinterpret_cast<float4*>(g_Z)[i] = z;
    }
}

// ---------------------------------------------------------------------------
// mma + ldmatrix wrappers
// ---------------------------------------------------------------------------
__device__ __forceinline__ void mma_bf16(float* c, const unsigned* a, const unsigned* b) {
    asm volatile(
        "mma.sync.aligned.m16n8k16.row.col.f32.bf16.bf16.f32 "
        "{%0,%1,%2,%3}, {%4,%5,%6,%7}, {%8,%9}, {%0,%1,%2,%3};"
        : "+f"(c[0]), "+f"(c[1]), "+f"(c[2]), "+f"(c[3])
        : "r"(a[0]), "r"(a[1]), "r"(a[2]), "r"(a[3]), "r"(b[0]), "r"(b[1]));
}
__device__ __forceinline__ void ldm_x4(unsigned* r, unsigned saddr) {
    asm volatile("ldmatrix.sync.aligned.m8n8.x4.shared.b16 {%0,%1,%2,%3}, [%4];"
                 : "=r"(r[0]), "=r"(r[1]), "=r"(r[2]), "=r"(r[3]) : "r"(saddr));
}

// ---------------------------------------------------------------------------
// gemm_dual: A full-K resident in smem (loaded ONCE), then 2 relations
// computed against it with W k-tiles streamed (R9 pipelined rhythm).
// Writes Te buffers bufbase, bufbase+1.
// ---------------------------------------------------------------------------
#define PAF    68   // A word pitch (full-K); 68 mod 32 = 4 -> conflict-free
#define WPITCH 20   // W k-tile word pitch (R9-proven)
#define DSM_WORDS (64 * PAF * 2 + 128 * WPITCH * 2)   // 13824
#define DSM_BYTES (DSM_WORDS * 4)                     // 55296

__global__ void __launch_bounds__(256, 3) gemm_dual(int woff0, int bufbase, int M) {
    extern __shared__ unsigned sm[];
    unsigned* Afh = sm;                          // [64][PAF]
    unsigned* Afl = sm + 64 * PAF;
    unsigned* Wkh = sm + 2 * 64 * PAF;           // [128][WPITCH]
    unsigned* Wkl = sm + 2 * 64 * PAF + 128 * WPITCH;

    const int tid    = threadIdx.x;
    const int lane   = tid & 31;
    const int wid    = tid >> 5;
    const int warp_m = wid >> 2;
    const int warp_n = wid & 3;
    const int m0     = blockIdx.x * 64;
    const int gq     = lane >> 2;
    const int tg     = lane & 3;
    const int lane8  = lane & 7;
    const int tsel   = lane >> 3;

    unsigned sAh = (unsigned)__cvta_generic_to_shared(Afh);
    unsigned sAl = (unsigned)__cvta_generic_to_shared(Afl);
    unsigned sWh = (unsigned)__cvta_generic_to_shared(Wkh);
    unsigned sWl = (unsigned)__cvta_generic_to_shared(Wkl);

    // ---- load A full-K once: 64 rows x 64 words (hi+lo) ----
    {
        int row = tid >> 2, q = tid & 3;
        int gr = m0 + row;
#pragma unroll
        for (int j = 0; j < 4; j++) {
            int w0 = q * 16 + j * 4;
            uint4 vh = make_uint4(0, 0, 0, 0), vl = make_uint4(0, 0, 0, 0);
            if (gr < M) {
                size_t s = (size_t)gr * 64 + w0;
                vh = *reinterpret_cast<const uint4*>(g_Ah + s);
                vl = *reinterpret_cast<const uint4*>(g_Al + s);
            }
            int d = row * PAF + w0;
            *reinterpret_cast<uint4*>(Afh + d) = vh;
            *reinterpret_cast<uint4*>(Afl + d) = vl;
        }
    }

#pragma unroll
    for (int rr = 0; rr < 2; rr++) {
        const unsigned* Wh = g_Wh + woff0 + rr * 8192;
        const unsigned* Wl = g_Wl + woff0 + rr * 8192;
        float* Te = g_TeA + (size_t)(bufbase + rr) * N_ENT * DIM;

        float acc[2][4][4];
#pragma unroll
        for (int i = 0; i < 2; i++)
#pragma unroll
            for (int j = 0; j < 4; j++)
#pragma unroll
                for (int k = 0; k < 4; k++) acc[i][j][k] = 0.f;

#pragma unroll
        for (int kt = 0; kt < 4; kt++) {
            const int K0 = kt * 16;
            __syncthreads();   // prior mma done reading Wk (and A stores visible on kt=0,rr=0)
            // ---- load W k-tile: 128 n x 16 words ----
#pragma unroll
            for (int i = 0; i < 2; i++) {
                int li = tid + i * 256;
                int n = li >> 2, q = li & 3;
                size_t s = (size_t)n * 64 + K0 + q * 4;
                int d = n * WPITCH + q * 4;
                *reinterpret_cast<uint4*>(Wkh + d) = *reinterpret_cast<const uint4*>(Wh + s);
                *reinterpret_cast<uint4*>(Wkl + d) = *reinterpret_cast<const uint4*>(Wl + s);
            }
            __syncthreads();

#pragma unroll
            for (int ks = 0; ks < 2; ks++) {
                const int kpb = ks * 8;
                unsigned ahi[2][4], alo[2][4];
#pragma unroll
                for (int mt = 0; mt < 2; mt++) {
                    int arow = warp_m * 32 + mt * 16 + (tsel & 1) * 8 + lane8;
                    int akp  = K0 + kpb + (tsel >> 1) * 4;
                    unsigned off = (unsigned)(arow * PAF + akp) * 4u;
                    ldm_x4(ahi[mt], sAh + off);
                    ldm_x4(alo[mt], sAl + off);
                }
#pragma unroll
                for (int np = 0; np < 2; np++) {
                    int brow = warp_n * 32 + np * 16 + (tsel >> 1) * 8 + lane8;
                    int bkp  = kpb + (tsel & 1) * 4;
                    unsigned off = (unsigned)(brow * WPITCH + bkp) * 4u;
                    unsigned bh[4], bl[4];
                    ldm_x4(bh, sWh + off);
                    ldm_x4(bl, sWl + off);
#pragma unroll
                    for (int nn = 0; nn < 2; nn++)
#pragma unroll
                        for (int mt = 0; mt < 2; mt++) {
                            float* c = acc[mt][np * 2 + nn];
                            mma_bf16(c, ahi[mt], &bh[nn * 2]);
                            mma_bf16(c, alo[mt], &bh[nn * 2]);
                            mma_bf16(c, ahi[mt], &bl[nn * 2]);
                        }
                }
            }
        }

        // epilogue: c0,c1 @ (row gq, cols 2tg,2tg+1); c2,c3 @ row gq+8
#pragma unroll
        for (int mt = 0; mt < 2; mt++) {
#pragma unroll
            for (int half = 0; half < 2; half++) {
                int gr = m0 + warp_m * 32 + mt * 16 + gq + half * 8;
                if (gr >= M) continue;
#pragma unroll
                for (int nt = 0; nt < 4; nt++) {
                    int col = warp_n * 32 + nt * 8 + 2 * tg;
                    float2 v = make_float2(acc[mt][nt][half * 2 + 0],
                                           acc[mt][nt][half * 2 + 1]);
                    *reinterpret_cast<float2*>(&Te[(size_t)gr * 128 + col]) = v;
                }
            }
        }
    }
}

// ---------------------------------------------------------------------------
// out_tc (R9-proven): X @ selfk with sigmoid(acc + Z[idx]) epilogue.
// ---------------------------------------------------------------------------
#define PITCH 20
__global__ void __launch_bounds__(256, 3) out_tc(int asel, int woff,
                                                 const int* __restrict__ idx,
                                                 float* __restrict__ out, int M) {
    __shared__ unsigned Ash[64 * PITCH], Asl[64 * PITCH];
    __shared__ unsigned Wsh[128 * PITCH], Wsl[128 * PITCH];

    const unsigned* Ah = asel == 1 ? g_Hh : g_Th;
    const unsigned* Al = asel == 1 ? g_Hl : g_Tl;
    const unsigned* Wh = g_Wh + woff;
    const unsigned* Wl = g_Wl + woff;

    const int tid    = threadIdx.x;
    const int lane   = tid & 31;
    const int wid    = tid >> 5;
    const int warp_m = wid >> 2;
    const int warp_n = wid & 3;
    const int m0     = blockIdx.x * 64;
    const int gq     = lane >> 2;
    const int tg     = lane & 3;
    const int lane8  = lane & 7;
    const int tsel   = lane >> 3;

    unsigned sAh = (unsigned)__cvta_generic_to_shared(Ash);
    unsigned sAl = (unsigned)__cvta_generic_to_shared(Asl);
    unsigned sWh = (unsigned)__cvta_generic_to_shared(Wsh);
    unsigned sWl = (unsigned)__cvta_generic_to_shared(Wsl);

    float acc[2][4][4];
#pragma unroll
    for (int i = 0; i < 2; i++)
#pragma unroll
        for (int j = 0; j < 4; j++)
#pragma unroll
            for (int k = 0; k < 4; k++) acc[i][j][k] = 0.f;

#pragma unroll
    for (int kt = 0; kt < 4; kt++) {
        const int K0 = kt * 16;
        {
            int row = tid >> 2, q = tid & 3;
            int gr = m0 + row;
            uint4 vh = make_uint4(0, 0, 0, 0), vl = make_uint4(0, 0, 0, 0);
            if (gr < M) {
                size_t s = (size_t)gr * 64 + K0 + q * 4;
                vh = *reinterpret_cast<const uint4*>(Ah + s);
                vl = *reinterpret_cast<const uint4*>(Al + s);
            }
            int d = row * PITCH + q * 4;
            *reinterpret_cast<uint4*>(Ash + d) = vh;
            *reinterpret_cast<uint4*>(Asl + d) = vl;
        }
#pragma unroll
        for (int i = 0; i < 2; i++) {
            int li = tid + i * 256;
            int n = li >> 2, q = li & 3;
            size_t s = (size_t)n * 64 + K0 + q * 4;
            int d = n * PITCH + q * 4;
            *reinterpret_cast<uint4*>(Wsh + d) = *reinterpret_cast<const uint4*>(Wh + s);
            *reinterpret_cast<uint4*>(Wsl + d) = *reinterpret_cast<const uint4*>(Wl + s);
        }
        __syncthreads();

#pragma unroll
        for (int ks = 0; ks < 2; ks++) {
            const int kpb = ks * 8;
            unsigned ahi[2][4], alo[2][4];
#pragma unroll
            for (int mt = 0; mt < 2; mt++) {
                int arow = warp_m * 32 + mt * 16 + (tsel & 1) * 8 + lane8;
                int akp  = kpb + (tsel >> 1) * 4;
                unsigned off = (unsigned)(arow * PITCH + akp) * 4u;
                ldm_x4(ahi[mt], sAh + off);
                ldm_x4(alo[mt], sAl + off);
            }
#pragma unroll
            for (int np = 0; np < 2; np++) {
                int brow = warp_n * 32 + np * 16 + (tsel >> 1) * 8 + lane8;
                int bkp  = kpb + (tsel & 1) * 4;
                unsigned off = (unsigned)(brow * PITCH + bkp) * 4u;
                unsigned bh[4], bl[4];
                ldm_x4(bh, sWh + off);
                ldm_x4(bl, sWl + off);
#pragma unroll
                for (int nn = 0; nn < 2; nn++)
#pragma unroll
                    for (int mt = 0; mt < 2; mt++) {
                        float* c = acc[mt][np * 2 + nn];
                        mma_bf16(c, ahi[mt], &bh[nn * 2]);
                        mma_bf16(c, alo[mt], &bh[nn * 2]);
                        mma_bf16(c, ahi[mt], &bl[nn * 2]);
                    }
            }
        }
        __syncthreads();
    }

#pragma unroll
    for (int mt = 0; mt < 2; mt++) {
#pragma unroll
        for (int half = 0; half < 2; half++) {
            int gr = m0 + warp_m * 32 + mt * 16 + gq + half * 8;
            if (gr >= M) continue;
            int node = __ldg(&idx[gr]);
#pragma unroll
            for (int nt = 0; nt < 4; nt++) {
                int col = warp_n * 32 + nt * 8 + 2 * tg;
                float2 z = *reinterpret_cast<const float2*>(&g_Z[(size_t)node * 128 + col]);
                float2 o;
                o.x = 1.f / (1.f + expf(-(acc[mt][nt][half * 2 + 0] + z.x)));
                o.y = 1.f / (1.f + expf(-(acc[mt][nt][half * 2 + 1] + z.y)));
                *reinterpret_cast<float2*>(&out[(size_t)gr * 128 + col]) = o;
            }
        }
    }
}

// ---------------------------------------------------------------------------
// Scatter (R9-proven, MLP=8), Te buffer selected by index 0..3
// ---------------------------------------------------------------------------
#define EPB 64
__global__ void __launch_bounds__(256) scatter_k(const int*   __restrict__ src,
                                                 const int*   __restrict__ dst,
                                                 const float* __restrict__ val,
                                                 int buf) {
    const float* Te = g_TeA + (size_t)buf * N_ENT * DIM;
    __shared__ int   sS[EPB];
    __shared__ int   sD[EPB];
    __shared__ float sV[EPB];
    const int base = blockIdx.x * EPB;
    const int tid  = threadIdx.x;
    if (tid < EPB)                sS[tid]           = __ldg(&src[base + tid]);
    else if (tid < 2 * EPB)       sD[tid - EPB]     = __ldg(&dst[base + tid - EPB]);
    else if (tid < 3 * EPB)       sV[tid - 2 * EPB] = __ldg(&val[base + tid - 2 * EPB]);
    __syncthreads();

    const int wid  = tid >> 5;
    const int lane = tid & 31;
    const int e0   = wid * 8;

    float4 t[8];
#pragma unroll
    for (int i = 0; i < 8; i++) {
        int d = sD[e0 + i];
        t[i] = *reinterpret_cast<const float4*>(&Te[(size_t)d * 128 + lane * 4]);
    }
#pragma unroll
    for (int i = 0; i < 8; i++) {
        float v = sV[e0 + i];
        float* zp = &g_Z[(size_t)sS[e0 + i] * 128 + lane * 4];
        asm volatile("red.global.add.v4.f32 [%0], {%1, %2, %3, %4};"
                     :: "l"(zp), "f"(t[i].x * v), "f"(t[i].y * v),
                        "f"(t[i].z * v), "f"(t[i].w * v)
                     : "memory");
    }
}

// ---------------------------------------------------------------------------
// Launch: 4 dual-relation gemms; each pair's scatters forked to s2.
// ---------------------------------------------------------------------------
extern "C" void kernel_launch(void* const* d_in, const int* in_sizes, int n_in,
                              void* d_out, int out_size) {
    const float* emb      = (const float*)d_in[0];
    const float* head_e   = (const float*)d_in[1];
    const float* tail_e   = (const float*)d_in[2];
    const float* relk     = (const float*)d_in[3];
    const float* selfk    = (const float*)d_in[4];
    const float* edge_val = (const float*)d_in[5];
    const int*   head_idx = (const int*)d_in[6];
    const int*   tail_idx = (const int*)d_in[7];
    const int*   edge_src = (const int*)d_in[8];
    const int*   edge_dst = (const int*)d_in[9];
    float*       out      = (float*)d_out;        // [2, B, 128], head first

    static bool init = false;
    static cudaStream_t s2;
    static cudaEvent_t e_g[4], e_s[4];
    if (!init) {   // first call is the uncaptured correctness run
        cudaFuncSetAttribute(gemm_dual, cudaFuncAttributeMaxDynamicSharedMemorySize, DSM_BYTES);
        cudaStreamCreateWithFlags(&s2, cudaStreamNonBlocking);
        for (int i = 0; i < 4; i++) {
            cudaEventCreateWithFlags(&e_g[i], cudaEventDisableTiming);
            cudaEventCreateWithFlags(&e_s[i], cudaEventDisableTiming);
        }
        init = true;
    }

    pack_rows<<<(N_ENT * 64 + 255) / 256, 256>>>(emb,    0, N_ENT * 64);
    pack_rows<<<(NB * 64 + 255) / 256, 256>>>(head_e, 1, NB * 64);
    pack_rows<<<(NB * 64 + 255) / 256, 256>>>(tail_e, 2, NB * 64);
    pack_w<<<dim3(32, NR), 256>>>(relk, 0);
    pack_w<<<dim3(32, 1), 256>>>(selfk, NR * 8192);
    zero_Z_k<<<2048, 256>>>();

    const int gemm_blocks = (N_ENT + 63) / 64;   // 1563
    const int scat_blocks = NE / EPB;            // 3125
    for (int j = 0; j < 4; j++) {
        int bufbase = (j & 1) * 2;
        if (j >= 2) cudaStreamWaitEvent(0, e_s[j - 2], 0);  // buffer pair reuse guard
        gemm_dual<<<gemm_blocks, 256, DSM_BYTES>>>(2 * j * 8192, bufbase, N_ENT);
        cudaEventRecord(e_g[j], 0);
        cudaStreamWaitEvent(s2, e_g[j], 0);
        for (int rr = 0; rr < 2; rr++) {
            int r = 2 * j + rr;
            scatter_k<<<scat_blocks, 256, 0, s2>>>(edge_src + (size_t)r * NE,
                                                   edge_dst + (size_t)r * NE,
                                                   edge_val + (size_t)r * NE,
                                                   bufbase + rr);
        }
        cudaEventRecord(e_s[j], s2);
    }
    cudaStreamWaitEvent(0, e_s[3], 0);   // join (s2 FIFO orders all scatters before it)

    const int out_blocks = (NB + 63) / 64;       // 782
    out_tc<<<out_blocks, 256>>>(1, NR * 8192, head_idx, out, NB);
    out_tc<<<out_blocks, 256>>>(2, NR * 8192, tail_idx, out + (size_t)NB * 128, NB);
}

// round 17
// speedup vs baseline: 1.3107x; 1.0418x over previous
#include <cuda_runtime.h>
#include <cuda_bf16.h>
#include <math.h>

#define N_ENT 100000
#define DIM   128
#define NB    50000
#define NR    8
#define NE    200000

// ---------------------------------------------------------------------------
// Device scratch
// ---------------------------------------------------------------------------
__device__ float    g_TeA[(size_t)4 * N_ENT * DIM];  // 4 Te buffers
__device__ float    g_Z  [(size_t)N_ENT * DIM];      // accumulator
// packed weights: [9 mats][n=128][kp=64], mat 8 = self kernel
__device__ unsigned g_Wh[9 * 128 * 64], g_Wl[9 * 128 * 64];

// ---------------------------------------------------------------------------
// bf16 split helpers
// ---------------------------------------------------------------------------
__device__ __forceinline__ void split_pack(float x, unsigned short& h, unsigned short& l) {
    __nv_bfloat16 hb = __float2bfloat16(x);
    float hf = __bfloat162float(hb);
    __nv_bfloat16 lb = __float2bfloat16(x - hf);
    h = __bfloat16_as_ushort(hb);
    l = __bfloat16_as_ushort(lb);
}
// split a float4 (4 consecutive k values) into 2 hi words + 2 lo words
__device__ __forceinline__ void split4(float4 v, unsigned* h, unsigned* l) {
    unsigned short h0, l0, h1, l1;
    split_pack(v.x, h0, l0); split_pack(v.y, h1, l1);
    h[0] = (unsigned)h0 | ((unsigned)h1 << 16);
    l[0] = (unsigned)l0 | ((unsigned)l1 << 16);
    split_pack(v.z, h0, l0); split_pack(v.w, h1, l1);
    h[1] = (unsigned)h0 | ((unsigned)h1 << 16);
    l[1] = (unsigned)l0 | ((unsigned)l1 << 16);
}

__global__ void __launch_bounds__(256) pack_w(const float* __restrict__ src,
                                              int dst_off) {
    int mat = blockIdx.y;
    const float* W = src + (size_t)mat * 128 * 128;
    int idx = blockIdx.x * 256 + threadIdx.x;   // 0..8191
    int n  = idx & 127;
    int kp = idx >> 7;                          // 0..63
    float a = W[(2 * kp) * 128 + n];
    float b = W[(2 * kp + 1) * 128 + n];
    unsigned short h0, l0, h1, l1;
    split_pack(a, h0, l0);
    split_pack(b, h1, l1);
    int w = dst_off + mat * 8192 + n * 64 + kp;
    g_Wh[w] = (unsigned)h0 | ((unsigned)h1 << 16);
    g_Wl[w] = (unsigned)l0 | ((unsigned)l1 << 16);
}

__global__ void __launch_bounds__(256) zero_Z_k() {
    const int n4 = N_ENT * DIM / 4;
    float4 z = make_float4(0.f, 0.f, 0.f, 0.f);
    for (int i = blockIdx.x * blockDim.x + threadIdx.x; i < n4;
         i += gridDim.x * blockDim.x) {
        reinterpret_cast<float4*>(g_Z)[i] = z;
    }
}

// ---------------------------------------------------------------------------
// mma + ldmatrix wrappers
// ---------------------------------------------------------------------------
__device__ __forceinline__ void mma_bf16(float* c, const unsigned* a, const unsigned* b) {
    asm volatile(
        "mma.sync.aligned.m16n8k16.row.col.f32.bf16.bf16.f32 "
        "{%0,%1,%2,%3}, {%4,%5,%6,%7}, {%8,%9}, {%0,%1,%2,%3};"
        : "+f"(c[0]), "+f"(c[1]), "+f"(c[2]), "+f"(c[3])
        : "r"(a[0]), "r"(a[1]), "r"(a[2]), "r"(a[3]), "r"(b[0]), "r"(b[1]));
}
__device__ __forceinline__ void ldm_x4(unsigned* r, unsigned saddr) {
    asm volatile("ldmatrix.sync.aligned.m8n8.x4.shared.b16 {%0,%1,%2,%3}, [%4];"
                 : "=r"(r[0]), "=r"(r[1]), "=r"(r[2]), "=r"(r[3]) : "r"(saddr));
}

// ---------------------------------------------------------------------------
// gemm_dual: fp32 A rows read directly, split to hi/lo bf16 in registers,
// full-K resident in smem (loaded ONCE); 2 relations computed against it
// with W k-tiles streamed (R9 pipelined rhythm). Writes Te bufbase, bufbase+1.
// ---------------------------------------------------------------------------
#define PAF    68   // A word pitch (full-K); 68 mod 32 = 4 -> conflict-free
#define WPITCH 20   // W k-tile word pitch (R9-proven)
#define DSM_WORDS (64 * PAF * 2 + 128 * WPITCH * 2)   // 13824
#define DSM_BYTES (DSM_WORDS * 4)                     // 55296

__global__ void __launch_bounds__(256, 3) gemm_dual(const float* __restrict__ A,
                                                    int woff0, int bufbase, int M) {
    extern __shared__ unsigned sm[];
    unsigned* Afh = sm;                          // [64][PAF]
    unsigned* Afl = sm + 64 * PAF;
    unsigned* Wkh = sm + 2 * 64 * PAF;           // [128][WPITCH]
    unsigned* Wkl = sm + 2 * 64 * PAF + 128 * WPITCH;

    const int tid    = threadIdx.x;
    const int lane   = tid & 31;
    const int wid    = tid >> 5;
    const int warp_m = wid >> 2;
    const int warp_n = wid & 3;
    const int m0     = blockIdx.x * 64;
    const int gq     = lane >> 2;
    const int tg     = lane & 3;
    const int lane8  = lane & 7;
    const int tsel   = lane >> 3;

    unsigned sAh = (unsigned)__cvta_generic_to_shared(Afh);
    unsigned sAl = (unsigned)__cvta_generic_to_shared(Afl);
    unsigned sWh = (unsigned)__cvta_generic_to_shared(Wkh);
    unsigned sWl = (unsigned)__cvta_generic_to_shared(Wkl);

    // ---- load A full-K once: fp32, split in registers. 4 thr/row. ----
    {
        int row = tid >> 2, q = tid & 3;
        int gr = m0 + row;
#pragma unroll
        for (int j = 0; j < 4; j++) {
            int w0 = q * 16 + j * 4;             // word offset (4 words = 8 floats)
            unsigned h[4] = {0, 0, 0, 0}, l[4] = {0, 0, 0, 0};
            if (gr < M) {
                const float* ap = A + (size_t)gr * 128 + 2 * w0;
                split4(*reinterpret_cast<const float4*>(ap),     h,     l);
                split4(*reinterpret_cast<const float4*>(ap + 4), h + 2, l + 2);
            }
            int d = row * PAF + w0;
            *reinterpret_cast<uint4*>(Afh + d) = make_uint4(h[0], h[1], h[2], h[3]);
            *reinterpret_cast<uint4*>(Afl + d) = make_uint4(l[0], l[1], l[2], l[3]);
        }
    }

#pragma unroll
    for (int rr = 0; rr < 2; rr++) {
        const unsigned* Wh = g_Wh + woff0 + rr * 8192;
        const unsigned* Wl = g_Wl + woff0 + rr * 8192;
        float* Te = g_TeA + (size_t)(bufbase + rr) * N_ENT * DIM;

        float acc[2][4][4];
#pragma unroll
        for (int i = 0; i < 2; i++)
#pragma unroll
            for (int j = 0; j < 4; j++)
#pragma unroll
                for (int k = 0; k < 4; k++) acc[i][j][k] = 0.f;

#pragma unroll
        for (int kt = 0; kt < 4; kt++) {
            const int K0 = kt * 16;
            __syncthreads();   // prior mma done reading Wk; A stores visible at rr=0,kt=0
            // ---- load W k-tile: 128 n x 16 words ----
#pragma unroll
            for (int i = 0; i < 2; i++) {
                int li = tid + i * 256;
                int n = li >> 2, q = li & 3;
                size_t s = (size_t)n * 64 + K0 + q * 4;
                int d = n * WPITCH + q * 4;
                *reinterpret_cast<uint4*>(Wkh + d) = *reinterpret_cast<const uint4*>(Wh + s);
                *reinterpret_cast<uint4*>(Wkl + d) = *reinterpret_cast<const uint4*>(Wl + s);
            }
            __syncthreads();

#pragma unroll
            for (int ks = 0; ks < 2; ks++) {
                const int kpb = ks * 8;
                unsigned ahi[2][4], alo[2][4];
#pragma unroll
                for (int mt = 0; mt < 2; mt++) {
                    int arow = warp_m * 32 + mt * 16 + (tsel & 1) * 8 + lane8;
                    int akp  = K0 + kpb + (tsel >> 1) * 4;
                    unsigned off = (unsigned)(arow * PAF + akp) * 4u;
                    ldm_x4(ahi[mt], sAh + off);
                    ldm_x4(alo[mt], sAl + off);
                }
#pragma unroll
                for (int np = 0; np < 2; np++) {
                    int brow = warp_n * 32 + np * 16 + (tsel >> 1) * 8 + lane8;
                    int bkp  = kpb + (tsel & 1) * 4;
                    unsigned off = (unsigned)(brow * WPITCH + bkp) * 4u;
                    unsigned bh[4], bl[4];
                    ldm_x4(bh, sWh + off);
                    ldm_x4(bl, sWl + off);
#pragma unroll
                    for (int nn = 0; nn < 2; nn++)
#pragma unroll
                        for (int mt = 0; mt < 2; mt++) {
                            float* c = acc[mt][np * 2 + nn];
                            mma_bf16(c, ahi[mt], &bh[nn * 2]);
                            mma_bf16(c, alo[mt], &bh[nn * 2]);
                            mma_bf16(c, ahi[mt], &bl[nn * 2]);
                        }
                }
            }
        }

        // epilogue: c0,c1 @ (row gq, cols 2tg,2tg+1); c2,c3 @ row gq+8
#pragma unroll
        for (int mt = 0; mt < 2; mt++) {
#pragma unroll
            for (int half = 0; half < 2; half++) {
                int gr = m0 + warp_m * 32 + mt * 16 + gq + half * 8;
                if (gr >= M) continue;
#pragma unroll
                for (int nt = 0; nt < 4; nt++) {
                    int col = warp_n * 32 + nt * 8 + 2 * tg;
                    float2 v = make_float2(acc[mt][nt][half * 2 + 0],
                                           acc[mt][nt][half * 2 + 1]);
                    *reinterpret_cast<float2*>(&Te[(size_t)gr * 128 + col]) = v;
                }
            }
        }
    }
}

// ---------------------------------------------------------------------------
// out_tc: fp32 X rows read directly, split in registers; k-tiles pipelined;
// epilogue sigmoid(acc + Z[idx]).
// ---------------------------------------------------------------------------
#define PITCH 20
__global__ void __launch_bounds__(256, 3) out_tc(const float* __restrict__ X,
                                                 int woff,
                                                 const int* __restrict__ idx,
                                                 float* __restrict__ out, int M) {
    __shared__ unsigned Ash[64 * PITCH], Asl[64 * PITCH];
    __shared__ unsigned Wsh[128 * PITCH], Wsl[128 * PITCH];

    const unsigned* Wh = g_Wh + woff;
    const unsigned* Wl = g_Wl + woff;

    const int tid    = threadIdx.x;
    const int lane   = tid & 31;
    const int wid    = tid >> 5;
    const int warp_m = wid >> 2;
    const int warp_n = wid & 3;
    const int m0     = blockIdx.x * 64;
    const int gq     = lane >> 2;
    const int tg     = lane & 3;
    const int lane8  = lane & 7;
    const int tsel   = lane >> 3;

    unsigned sAh = (unsigned)__cvta_generic_to_shared(Ash);
    unsigned sAl = (unsigned)__cvta_generic_to_shared(Asl);
    unsigned sWh = (unsigned)__cvta_generic_to_shared(Wsh);
    unsigned sWl = (unsigned)__cvta_generic_to_shared(Wsl);

    float acc[2][4][4];
#pragma unroll
    for (int i = 0; i < 2; i++)
#pragma unroll
        for (int j = 0; j < 4; j++)
#pragma unroll
            for (int k = 0; k < 4; k++) acc[i][j][k] = 0.f;

#pragma unroll
    for (int kt = 0; kt < 4; kt++) {
        const int K0 = kt * 16;
        {
            int row = tid >> 2, q = tid & 3;
            int gr = m0 + row;
            int w0 = K0 + q * 4;
            unsigned h[4] = {0, 0, 0, 0}, l[4] = {0, 0, 0, 0};
            if (gr < M) {
                const float* ap = X + (size_t)gr * 128 + 2 * w0;
                split4(*reinterpret_cast<const float4*>(ap),     h,     l);
                split4(*reinterpret_cast<const float4*>(ap + 4), h + 2, l + 2);
            }
            int d = row * PITCH + q * 4;
            *reinterpret_cast<uint4*>(Ash + d) = make_uint4(h[0], h[1], h[2], h[3]);
            *reinterpret_cast<uint4*>(Asl + d) = make_uint4(l[0], l[1], l[2], l[3]);
        }
#pragma unroll
        for (int i = 0; i < 2; i++) {
            int li = tid + i * 256;
            int n = li >> 2, q = li & 3;
            size_t s = (size_t)n * 64 + K0 + q * 4;
            int d = n * PITCH + q * 4;
            *reinterpret_cast<uint4*>(Wsh + d) = *reinterpret_cast<const uint4*>(Wh + s);
            *reinterpret_cast<uint4*>(Wsl + d) = *reinterpret_cast<const uint4*>(Wl + s);
        }
        __syncthreads();

#pragma unroll
        for (int ks = 0; ks < 2; ks++) {
            const int kpb = ks * 8;
            unsigned ahi[2][4], alo[2][4];
#pragma unroll
            for (int mt = 0; mt < 2; mt++) {
                int arow = warp_m * 32 + mt * 16 + (tsel & 1) * 8 + lane8;
                int akp  = kpb + (tsel >> 1) * 4;
                unsigned off = (unsigned)(arow * PITCH + akp) * 4u;
                ldm_x4(ahi[mt], sAh + off);
                ldm_x4(alo[mt], sAl + off);
            }
#pragma unroll
            for (int np = 0; np < 2; np++) {
                int brow = warp_n * 32 + np * 16 + (tsel >> 1) * 8 + lane8;
                int bkp  = kpb + (tsel & 1) * 4;
                unsigned off = (unsigned)(brow * PITCH + bkp) * 4u;
                unsigned bh[4], bl[4];
                ldm_x4(bh, sWh + off);
                ldm_x4(bl, sWl + off);
#pragma unroll
                for (int nn = 0; nn < 2; nn++)
#pragma unroll
                    for (int mt = 0; mt < 2; mt++) {
                        float* c = acc[mt][np * 2 + nn];
                        mma_bf16(c, ahi[mt], &bh[nn * 2]);
                        mma_bf16(c, alo[mt], &bh[nn * 2]);
                        mma_bf16(c, ahi[mt], &bl[nn * 2]);
                    }
            }
        }
        __syncthreads();
    }

#pragma unroll
    for (int mt = 0; mt < 2; mt++) {
#pragma unroll
        for (int half = 0; half < 2; half++) {
            int gr = m0 + warp_m * 32 + mt * 16 + gq + half * 8;
            if (gr >= M) continue;
            int node = __ldg(&idx[gr]);
#pragma unroll
            for (int nt = 0; nt < 4; nt++) {
                int col = warp_n * 32 + nt * 8 + 2 * tg;
                float2 z = *reinterpret_cast<const float2*>(&g_Z[(size_t)node * 128 + col]);
                float2 o;
                o.x = 1.f / (1.f + expf(-(acc[mt][nt][half * 2 + 0] + z.x)));
                o.y = 1.f / (1.f + expf(-(acc[mt][nt][half * 2 + 1] + z.y)));
                *reinterpret_cast<float2*>(&out[(size_t)gr * 128 + col]) = o;
            }
        }
    }
}

// ---------------------------------------------------------------------------
// Scatter (R9-proven, MLP=8), Te buffer selected by index 0..3
// ---------------------------------------------------------------------------
#define EPB 64
__global__ void __launch_bounds__(256) scatter_k(const int*   __restrict__ src,
                                                 const int*   __restrict__ dst,
                                                 const float* __restrict__ val,
                                                 int buf) {
    const float* Te = g_TeA + (size_t)buf * N_ENT * DIM;
    __shared__ int   sS[EPB];
    __shared__ int   sD[EPB];
    __shared__ float sV[EPB];
    const int base = blockIdx.x * EPB;
    const int tid  = threadIdx.x;
    if (tid < EPB)                sS[tid]           = __ldg(&src[base + tid]);
    else if (tid < 2 * EPB)       sD[tid - EPB]     = __ldg(&dst[base + tid - EPB]);
    else if (tid < 3 * EPB)       sV[tid - 2 * EPB] = __ldg(&val[base + tid - 2 * EPB]);
    __syncthreads();

    const int wid  = tid >> 5;
    const int lane = tid & 31;
    const int e0   = wid * 8;

    float4 t[8];
#pragma unroll
    for (int i = 0; i < 8; i++) {
        int d = sD[e0 + i];
        t[i] = *reinterpret_cast<const float4*>(&Te[(size_t)d * 128 + lane * 4]);
    }
#pragma unroll
    for (int i = 0; i < 8; i++) {
        float v = sV[e0 + i];
        float* zp = &g_Z[(size_t)sS[e0 + i] * 128 + lane * 4];
        asm volatile("red.global.add.v4.f32 [%0], {%1, %2, %3, %4};"
                     :: "l"(zp), "f"(t[i].x * v), "f"(t[i].y * v),
                        "f"(t[i].z * v), "f"(t[i].w * v)
                     : "memory");
    }
}

// ---------------------------------------------------------------------------
// Launch: 4 dual-relation gemms; each pair's scatters forked to s2.
// ---------------------------------------------------------------------------
extern "C" void kernel_launch(void* const* d_in, const int* in_sizes, int n_in,
                              void* d_out, int out_size) {
    const float* emb      = (const float*)d_in[0];
    const float* head_e   = (const float*)d_in[1];
    const float* tail_e   = (const float*)d_in[2];
    const float* relk     = (const float*)d_in[3];
    const float* selfk    = (const float*)d_in[4];
    const float* edge_val = (const float*)d_in[5];
    const int*   head_idx = (const int*)d_in[6];
    const int*   tail_idx = (const int*)d_in[7];
    const int*   edge_src = (const int*)d_in[8];
    const int*   edge_dst = (const int*)d_in[9];
    float*       out      = (float*)d_out;        // [2, B, 128], head first

    static bool init = false;
    static cudaStream_t s2;
    static cudaEvent_t e_g[4], e_s[4];
    if (!init) {   // first call is the uncaptured correctness run
        cudaFuncSetAttribute(gemm_dual, cudaFuncAttributeMaxDynamicSharedMemorySize, DSM_BYTES);
        cudaStreamCreateWithFlags(&s2, cudaStreamNonBlocking);
        for (int i = 0; i < 4; i++) {
            cudaEventCreateWithFlags(&e_g[i], cudaEventDisableTiming);
            cudaEventCreateWithFlags(&e_s[i], cudaEventDisableTiming);
        }
        init = true;
    }

    pack_w<<<dim3(32, NR), 256>>>(relk, 0);
    pack_w<<<dim3(32, 1), 256>>>(selfk, NR * 8192);
    zero_Z_k<<<2048, 256>>>();

    const int gemm_blocks = (N_ENT + 63) / 64;   // 1563
    const int scat_blocks = NE / EPB;            // 3125
    for (int j = 0; j < 4; j++) {
        int bufbase = (j & 1) * 2;
        if (j >= 2) cudaStreamWaitEvent(0, e_s[j - 2], 0);  // buffer pair reuse guard
        gemm_dual<<<gemm_blocks, 256, DSM_BYTES>>>(emb, 2 * j * 8192, bufbase, N_ENT);
        cudaEventRecord(e_g[j], 0);
        cudaStreamWaitEvent(s2, e_g[j], 0);
        for (int rr = 0; rr < 2; rr++) {
            int r = 2 * j + rr;
            scatter_k<<<scat_blocks, 256, 0, s2>>>(edge_src + (size_t)r * NE,
                                                   edge_dst + (size_t)r * NE,
                                                   edge_val + (size_t)r * NE,
                                                   bufbase + rr);
        }
        cudaEventRecord(e_s[j], s2);
    }
    cudaStreamWaitEvent(0, e_s[3], 0);   // join (s2 FIFO orders all scatters before it)

    const int out_blocks = (NB + 63) / 64;       // 782
    out_tc<<<out_blocks, 256>>>(head_e, NR * 8192, head_idx, out, NB);
    out_tc<<<out_blocks, 256>>>(tail_e, NR * 8192, tail_idx, out + (size_t)NB * 128, NB);
}